// round 17
// baseline (speedup 1.0000x reference)
#include <cuda_runtime.h>
#include <math.h>
#include <stdint.h>

// Problem dims
#define Bb   64
#define Tt   2048
#define INx  64
#define Hh   512
#define OUTD 32
#define K1   576      // INx + Hh
#define NCTA 132      // 4 sets x 33 CTAs
#define SETS 4
#define CPS  33       // CTAs per set: lc 0..31 workers, lc 32 = y
#define NGRP 8        // 8 independent groups of 8 batch rows (2 per set: A,B)
#define BG2  8        // batch rows per group
#define NTHR 512

typedef unsigned long long ull;

// ---- persistent device scratch ----
__device__ float g_x  [Hh * Bb];               // state, transposed [k][m]
__device__ float g_xfT[Hh * Bb];               // f*x, transposed  [k][m]
__device__ float g_z  [Hh * Bb];               // z gate           [j][m]
__device__ float g_uT [(size_t)Tt * INx * Bb]; // u transposed: [t][i][m]
__device__ unsigned g_bar;                     // one-time init barrier
__device__ unsigned g_c1[NGRP * 32];           // phase-1 done (33 arrivals/t)
__device__ unsigned g_c2[NGRP * 32];           // x updated   (32 arrivals/t)

// SMEM layout (floats)
#define OFF_W1  0        // 576*32 = 18432  (y-CTA: wy 512*32 = 16384 fits here)
#define OFF_W2  18432    // 576*16 = 9216
#define OFF_RED 27648    // 32*264 = 8448 (P2 uses 32*136; transpose tile 4160)
#define OFF_B1  36096    // 32
#define OFF_B2  36128    // 16
#define OFF_BY  36144    // 32
#define SMEM_FLOATS 36176
#define SMEM_BYTES  (SMEM_FLOATS * 4)

__device__ __forceinline__ ull bcast2(float v) {
  ull r;
  asm("mov.b64 %0, {%1, %1};" : "=l"(r) : "r"(__float_as_uint(v)));
  return r;
}
__device__ __forceinline__ unsigned poll_at(const unsigned* p) {
  unsigned v;
  asm volatile("ld.acquire.gpu.global.u32 %0, [%1];" : "=r"(v) : "l"(p) : "memory");
  return v;
}
__device__ __forceinline__ void arrive_release(unsigned* p) {
  asm volatile("red.release.gpu.global.add.u32 [%0], %1;" :: "l"(p), "r"(1u) : "memory");
}
__device__ __forceinline__ void unpack2(ull a, float& lo, float& hi) {
  unsigned l, h;
  asm("mov.b64 {%0,%1}, %2;" : "=r"(l), "=r"(h) : "l"(a));
  lo = __uint_as_float(l); hi = __uint_as_float(h);
}
#define FMA2(a, x, w) asm("fma.rn.f32x2 %0, %1, %2, %0;" : "+l"(a) : "l"(x), "l"(w))

__global__ void __launch_bounds__(NTHR, 1) gru_main(
    const float* __restrict__ u,
    const float* __restrict__ x0,
    const float* __restrict__ kernel_fz, const float* __restrict__ bias_fz,
    const float* __restrict__ kernel_r,  const float* __restrict__ bias_r,
    const float* __restrict__ W_out,     const float* __restrict__ b_out,
    float* __restrict__ out)
{
  extern __shared__ float smem[];
  float* s_w1  = smem + OFF_W1;   // [kk][32]: kk 0..511 x-rows, 512..575 u-rows
  float* s_w2  = smem + OFF_W2;   // [kk][16]
  float* s_red = smem + OFF_RED;  // P1/y: [ks][m(8)][33]; P2: [ks][m(8)][17]
  float* s_b1  = smem + OFF_B1;
  float* s_b2  = smem + OFF_B2;
  float* s_by  = smem + OFF_BY;

  const int tid = threadIdx.x;
  const int cid = blockIdx.x;
  const int set = cid / CPS;
  const int lc  = cid - set * CPS;      // 0..32
  const int gbA = set * 16;             // group A rows [gbA, gbA+8)
  const int gbB = set * 16 + 8;         // group B rows
  const int mg  = tid & 3;              // m-pair (rows 2mg, 2mg+1 of group)
  const int cs  = (tid >> 2) & 3;       // column split
  const int ks  = tid >> 4;             // K-slice 0..31 (16 x-rows + 2 u-rows)
  const int m0  = 2 * mg;
  unsigned* c1A = &g_c1[(set * 2 + 0) * 32];
  unsigned* c1B = &g_c1[(set * 2 + 1) * 32];
  unsigned* c2A = &g_c2[(set * 2 + 0) * 32];
  unsigned* c2B = &g_c2[(set * 2 + 1) * 32];

  // ---- stationary weights ----
  if (lc < 32) {
    for (int i = tid; i < K1 * 32; i += NTHR) {
      int kk = i / 32, n = i % 32;
      int row = (kk < Hh) ? (INx + kk) : (kk - Hh);   // [u | x] concat order
      s_w1[i] = kernel_fz[row * (2 * Hh) + lc * 32 + n];
    }
    for (int i = tid; i < K1 * 16; i += NTHR) {
      int kk = i / 16, n = i % 16;
      int row = (kk < Hh) ? (INx + kk) : (kk - Hh);
      s_w2[i] = kernel_r[row * Hh + lc * 16 + n];
    }
    if (tid < 32) s_b1[tid] = bias_fz[lc * 32 + tid];
    if (tid < 16) s_b2[tid] = bias_r[lc * 16 + tid];
  } else {
    for (int i = tid; i < Hh * 32; i += NTHR) {
      int kk = i / 32, n = i % 32;
      smem[OFF_W1 + i] = W_out[n * Hh + kk];
    }
    if (tid < OUTD) s_by[tid] = b_out[tid];
  }

  // ---- in-kernel init: x0 -> g_x ----
  for (int idx = cid * NTHR + tid; idx < Hh * Bb; idx += NCTA * NTHR) {
    int k = idx >> 6, mm = idx & 63;
    g_x[idx] = x0[mm * Hh + k];
  }

  // ---- in-kernel u transpose ----
  {
    float* tile = s_red;                 // 4160 floats fits
    __syncthreads();
    for (int t = cid; t < Tt; t += NCTA) {
      for (int idx = tid; idx < INx * Bb; idx += NTHR) {
        int mm = idx >> 6, i = idx & 63;
        tile[mm * 65 + i] = u[((size_t)mm * Tt + t) * INx + i];
      }
      __syncthreads();
      for (int idx = tid; idx < INx * Bb; idx += NTHR) {
        g_uT[(size_t)t * (INx * Bb) + idx] = tile[(idx & 63) * 65 + (idx >> 6)];
      }
      __syncthreads();
    }
  }

  // ---- one-time global barrier ----
  __threadfence();
  __syncthreads();
  if (tid == 0) atomicAdd(&g_bar, 1u);
  if (tid == 0) { while (poll_at(&g_bar) < NCTA) { } }
  __syncthreads();

  if (lc < 32) {
    // =============== worker CTA: interleaved groups A,B ===============
    for (int t = 0; t < Tt; t++) {
      const float* uT_t = g_uT + (size_t)t * (INx * Bb);

      #pragma unroll 1
      for (int gsel = 0; gsel < 2; gsel++) {
        // --- P1(group): fz cols [lc*32, +32) ---
        int gb = gsel ? gbB : gbA;
        if (gsel) {  // before touching x(B,t): B's update of t-1 must be done
          if (tid == 0) { unsigned need = 32u * t; while (poll_at(c2B) < need) { } }
          __syncthreads();
        }
        ull acc[8];
        #pragma unroll
        for (int p = 0; p < 8; p++) acc[p] = 0ull;
        { // u-seg: rows 512 + ks*2 + {0,1}
          const float2* up = (const float2*)(uT_t + (ks * 2) * Bb + gb + m0);
          const float*  wp = s_w1 + (Hh + ks * 2) * 32 + cs * 8;
          #pragma unroll
          for (int k = 0; k < 2; k++) {
            float2 xv = up[k * (Bb / 2)];
            ull x0b = bcast2(xv.x), x1b = bcast2(xv.y);
            const ulonglong2* wv = (const ulonglong2*)(wp + k * 32);
            ulonglong2 wA = wv[0], wB = wv[1];
            FMA2(acc[0], x0b, wA.x); FMA2(acc[1], x0b, wA.y);
            FMA2(acc[2], x0b, wB.x); FMA2(acc[3], x0b, wB.y);
            FMA2(acc[4], x1b, wA.x); FMA2(acc[5], x1b, wA.y);
            FMA2(acc[6], x1b, wB.x); FMA2(acc[7], x1b, wB.y);
          }
        }
        { // x-seg: rows [ks*16, +16)
          const float2* xp = (const float2*)(g_x + (ks * 16) * Bb + gb + m0);
          const float*  wp = s_w1 + (ks * 16) * 32 + cs * 8;
          #pragma unroll 8
          for (int k = 0; k < 16; k++) {
            float2 xv = __ldcg(xp + k * (Bb / 2));
            ull x0b = bcast2(xv.x), x1b = bcast2(xv.y);
            const ulonglong2* wv = (const ulonglong2*)(wp + k * 32);
            ulonglong2 wA = wv[0], wB = wv[1];
            FMA2(acc[0], x0b, wA.x); FMA2(acc[1], x0b, wA.y);
            FMA2(acc[2], x0b, wB.x); FMA2(acc[3], x0b, wB.y);
            FMA2(acc[4], x1b, wA.x); FMA2(acc[5], x1b, wA.y);
            FMA2(acc[6], x1b, wB.x); FMA2(acc[7], x1b, wB.y);
          }
        }
        { // store partials [ks][m][33] — conflict-free scalar stores
          float* rp = s_red + ks * 264 + m0 * 33;
          int colb = cs * 8;
          #pragma unroll
          for (int p = 0; p < 4; p++) {
            float e0, o0, e1, o1;
            unpack2(acc[p],     e0, o0);
            unpack2(acc[4 + p], e1, o1);
            rp[colb + 2 * p]          = e0;
            rp[colb + 2 * p + 1]      = o0;
            rp[33 + colb + 2 * p]     = e1;
            rp[33 + colb + 2 * p + 1] = o1;
          }
        }
        __syncthreads();
        if (tid < 256) { // epilogue: 8 batch x 32 cols
          int mm = tid & 7, n = tid >> 3;
          float s = s_b1[n];
          #pragma unroll
          for (int q = 0; q < 32; q++) s += s_red[q * 264 + mm * 33 + n];
          int c = lc * 32 + n;
          if (c < Hh) {
            float f = 1.0f / (1.0f + expf(-s));
            g_xfT[c * Bb + gb + mm] = f * __ldcg(&g_x[c * Bb + gb + mm]);
          } else {
            g_z[(c - Hh) * Bb + gb + mm] = 1.0f / (1.0f + expf(-s));
          }
        }
        __syncthreads();
        if (tid == 0) arrive_release(gsel ? c1B : c1A);
      }

      #pragma unroll 1
      for (int gsel = 0; gsel < 2; gsel++) {
        // --- P2(group): r cols [lc*16, +16) + state update ---
        int gb = gsel ? gbB : gbA;
        unsigned* c1 = gsel ? c1B : c1A;
        if (tid == 0) { unsigned need = 33u * (t + 1); while (poll_at(c1) < need) { } }
        __syncthreads();
        ull acc2[4] = {0ull, 0ull, 0ull, 0ull};
        { // u-seg
          const float2* up = (const float2*)(uT_t + (ks * 2) * Bb + gb + m0);
          const float*  wp = s_w2 + (Hh + ks * 2) * 16 + cs * 4;
          #pragma unroll
          for (int k = 0; k < 2; k++) {
            float2 xv = up[k * (Bb / 2)];
            ull x0b = bcast2(xv.x), x1b = bcast2(xv.y);
            ulonglong2 wA = *(const ulonglong2*)(wp + k * 16);
            FMA2(acc2[0], x0b, wA.x); FMA2(acc2[1], x0b, wA.y);
            FMA2(acc2[2], x1b, wA.x); FMA2(acc2[3], x1b, wA.y);
          }
        }
        { // f*x seg
          const float2* xp = (const float2*)(g_xfT + (ks * 16) * Bb + gb + m0);
          const float*  wp = s_w2 + (ks * 16) * 16 + cs * 4;
          #pragma unroll 8
          for (int k = 0; k < 16; k++) {
            float2 xv = __ldcg(xp + k * (Bb / 2));
            ull x0b = bcast2(xv.x), x1b = bcast2(xv.y);
            ulonglong2 wA = *(const ulonglong2*)(wp + k * 16);
            FMA2(acc2[0], x0b, wA.x); FMA2(acc2[1], x0b, wA.y);
            FMA2(acc2[2], x1b, wA.x); FMA2(acc2[3], x1b, wA.y);
          }
        }
        { // store partials [ks][m][17]
          float* rp = s_red + ks * 136 + m0 * 17;
          int colb = cs * 4;
          #pragma unroll
          for (int p = 0; p < 2; p++) {
            float e0, o0, e1, o1;
            unpack2(acc2[p],     e0, o0);
            unpack2(acc2[2 + p], e1, o1);
            rp[colb + 2 * p]          = e0;
            rp[colb + 2 * p + 1]      = o0;
            rp[17 + colb + 2 * p]     = e1;
            rp[17 + colb + 2 * p + 1] = o1;
          }
        }
        __syncthreads();
        if (tid < 128) { // 8 batch x 16 cols: update
          int mm = tid & 7, n = tid >> 3;
          float s = s_b2[n];
          #pragma unroll
          for (int q = 0; q < 32; q++) s += s_red[q * 136 + mm * 17 + n];
          int j = lc * 16 + n;
          float r  = tanhf(s);
          float z  = __ldcg(&g_z[j * Bb + gb + mm]);
          float xo = __ldcg(&g_x[j * Bb + gb + mm]);
          g_x[j * Bb + gb + mm] = (1.0f - z) * xo + z * r;
        }
        __syncthreads();
        if (tid == 0) arrive_release(gsel ? c2B : c2A);
      }

      // before P1(A, t+1): A's update must be complete
      if (tid == 0) { unsigned need = 32u * (t + 1); while (poll_at(c2A) < need) { } }
      __syncthreads();
    }
  } else {
    // =============== y-CTA: y(t) = x(t) @ W_out^T + b_out ===============
    const float* s_wy = smem + OFF_W1;
    for (int t = 0; t < Tt; t++) {
      #pragma unroll 1
      for (int gsel = 0; gsel < 2; gsel++) {
        int gb = gsel ? gbB : gbA;
        unsigned* c2 = gsel ? c2B : c2A;
        if (tid == 0) { unsigned need = 32u * t; while (poll_at(c2) < need) { } }
        __syncthreads();
        ull acc[8];
        #pragma unroll
        for (int p = 0; p < 8; p++) acc[p] = 0ull;
        {
          const float2* xp = (const float2*)(g_x + (ks * 16) * Bb + gb + m0);
          const float*  wp = s_wy + (ks * 16) * 32 + cs * 8;
          #pragma unroll 8
          for (int k = 0; k < 16; k++) {
            float2 xv = __ldcg(xp + k * (Bb / 2));
            ull x0b = bcast2(xv.x), x1b = bcast2(xv.y);
            const ulonglong2* wv = (const ulonglong2*)(wp + k * 32);
            ulonglong2 wA = wv[0], wB = wv[1];
            FMA2(acc[0], x0b, wA.x); FMA2(acc[1], x0b, wA.y);
            FMA2(acc[2], x0b, wB.x); FMA2(acc[3], x0b, wB.y);
            FMA2(acc[4], x1b, wA.x); FMA2(acc[5], x1b, wA.y);
            FMA2(acc[6], x1b, wB.x); FMA2(acc[7], x1b, wB.y);
          }
        }
        {
          float* rp = s_red + ks * 264 + m0 * 33;
          int colb = cs * 8;
          #pragma unroll
          for (int p = 0; p < 4; p++) {
            float e0, o0, e1, o1;
            unpack2(acc[p],     e0, o0);
            unpack2(acc[4 + p], e1, o1);
            rp[colb + 2 * p]          = e0;
            rp[colb + 2 * p + 1]      = o0;
            rp[33 + colb + 2 * p]     = e1;
            rp[33 + colb + 2 * p + 1] = o1;
          }
        }
        __syncthreads();
        if (tid < 256) {
          int mm = tid & 7, n = tid >> 3;
          float s = s_by[n];
          #pragma unroll
          for (int q = 0; q < 32; q++) s += s_red[q * 264 + mm * 33 + n];
          out[((size_t)(gb + mm) * Tt + t) * OUTD + n] = s;
        }
        __syncthreads();
        if (tid == 0) arrive_release(gsel ? c1B : c1A);
      }
    }
  }
}

// Runs BEFORE gru_main: resets counters; keeps gru_main as ncu launch #6.
__global__ void zero_bar_kernel() {
  g_bar = 0u;
  for (int g = 0; g < NGRP; g++) { g_c1[g * 32] = 0u; g_c2[g * 32] = 0u; }
}

extern "C" void kernel_launch(void* const* d_in, const int* in_sizes, int n_in,
                              void* d_out, int out_size) {
  const float *u = 0, *x0 = 0, *kernel_fz = 0, *bias_fz = 0,
              *kernel_r = 0, *bias_r = 0, *W_out = 0, *b_out = 0;
  for (int i = 0; i < n_in; i++) {
    const float* p = (const float*)d_in[i];
    switch (in_sizes[i]) {
      case 8388608: u         = p; break;
      case 32768:   x0        = p; break;
      case 589824:  kernel_fz = p; break;
      case 1024:    bias_fz   = p; break;
      case 294912:  kernel_r  = p; break;
      case 512:     bias_r    = p; break;
      case 16384:   W_out     = p; break;
      case 32:      b_out     = p; break;
      default: break;
    }
  }
  if (!u || !x0 || !kernel_fz || !bias_fz || !kernel_r || !bias_r || !W_out || !b_out) {
    u         = (const float*)d_in[0];
    x0        = (const float*)d_in[1];
    kernel_fz = (const float*)d_in[2];
    bias_fz   = (const float*)d_in[3];
    kernel_r  = (const float*)d_in[4];
    bias_r    = (const float*)d_in[5];
    W_out     = (const float*)d_in[6];
    b_out     = (const float*)d_in[7];
  }
  float* out = (float*)d_out;

  static int smem_set = 0;
  if (!smem_set) {
    cudaFuncSetAttribute(gru_main, cudaFuncAttributeMaxDynamicSharedMemorySize,
                         SMEM_BYTES);
    smem_set = 1;
  }

  zero_bar_kernel<<<1, 1>>>();

  void* args[] = { (void*)&u, (void*)&x0,
                   (void*)&kernel_fz, (void*)&bias_fz, (void*)&kernel_r,
                   (void*)&bias_r,    (void*)&W_out,   (void*)&b_out,
                   (void*)&out };
  cudaLaunchCooperativeKernel((const void*)gru_main, dim3(NCTA), dim3(NTHR),
                              args, SMEM_BYTES, (cudaStream_t)0);
}